// round 13
// baseline (speedup 1.0000x reference)
#include <cuda_runtime.h>
#include <cuda_fp16.h>
#include <cstdint>

// ---------------------------------------------------------------------------
// GPTQ 4-bit dequant GEMM, warp-specialized, fp16 mma.sync, fp32 accum.
// Kernel 1: A fp32->fp16 into __device__ scratch.
// Kernel 2: CTA tile 128x128x64. Warps 0-3 consume (64x64 each, pure MMA),
// warps 4-7 produce (cp.async A + LDG/dequant/STS B). 3-stage mbarrier ring.
// Smem rows 128B, XOR-8 16B-chunk swizzle.
// ---------------------------------------------------------------------------

__device__ __align__(16) __half g_A16[4096ull * 4096ull];   // scratch (32 MB)

#define LDSM4(R0,R1,R2,R3,addr) \
  asm volatile("ldmatrix.sync.aligned.m8n8.x4.shared.b16 {%0,%1,%2,%3}, [%4];" \
    : "=r"(R0),"=r"(R1),"=r"(R2),"=r"(R3) : "r"(addr))

#define MMA16(Cr,A0,A1,A2,A3,B0,B1) \
  asm volatile("mma.sync.aligned.m16n8k16.row.col.f32.f16.f16.f32 " \
    "{%0,%1,%2,%3},{%4,%5,%6,%7},{%8,%9},{%0,%1,%2,%3};" \
    : "+f"(Cr[0]),"+f"(Cr[1]),"+f"(Cr[2]),"+f"(Cr[3]) \
    : "r"(A0),"r"(A1),"r"(A2),"r"(A3),"r"(B0),"r"(B1))

#define CPASYNC16(dst, src) \
  asm volatile("cp.async.cg.shared.global [%0], [%1], 16;" :: "r"(dst), "l"(src))
#define CPCOMMIT() asm volatile("cp.async.commit_group;" ::: "memory")
#define CPWAIT0()  asm volatile("cp.async.wait_group 0;" ::: "memory")

#define MBAR_INIT(a, n) \
  asm volatile("mbarrier.init.shared.b64 [%0], %1;" :: "r"(a), "r"(n) : "memory")
#define MBAR_ARRIVE(a) \
  asm volatile("mbarrier.arrive.shared.b64 _, [%0];" :: "r"(a) : "memory")
#define MBAR_WAIT(a, ph) \
  asm volatile("{\n\t.reg .pred P;\n\tW%=:\n\t" \
    "mbarrier.try_wait.parity.acquire.cta.shared::cta.b64 P, [%0], %1;\n\t" \
    "@!P bra W%=;\n\t}" :: "r"(a), "r"(ph) : "memory")

__device__ __forceinline__ uint32_t f16x2(float lo, float hi){
  uint32_t r; asm("cvt.rn.f16x2.f32 %0, %2, %1;" : "=r"(r) : "f"(lo), "f"(hi)); return r;
}

// ---- kernel 1: A fp32 -> fp16 ----
__global__ void __launch_bounds__(256)
conv_a_kernel(const float* __restrict__ A, int total8){
  int i = blockIdx.x * blockDim.x + threadIdx.x;
  if (i >= total8) return;
  const float4* p = reinterpret_cast<const float4*>(A);
  float4 v0 = p[2*i], v1 = p[2*i+1];
  uint4 o;
  o.x = f16x2(v0.x, v0.y); o.y = f16x2(v0.z, v0.w);
  o.z = f16x2(v1.x, v1.y); o.w = f16x2(v1.z, v1.w);
  reinterpret_cast<uint4*>(g_A16)[i] = o;
}

// ---- kernel 2: warp-specialized GEMM ----
__global__ void __launch_bounds__(256, 1)
gptq_ws(const int* __restrict__ QW, const float* __restrict__ SC,
        const int* __restrict__ QZ, float* __restrict__ C,
        int M, int N, int K)
{
  // smem: 3 stages x (A 128x128B = 16KB, B 128x128B = 16KB) + mbarriers
  extern __shared__ char smem[];
  const int STAGE = 32768;
  const uint32_t sbase = (uint32_t)__cvta_generic_to_shared(smem);
  const uint32_t mbb   = sbase + 3*STAGE;       // full[s]=+16s, empty[s]=+16s+8

  const int tid  = threadIdx.x;
  const int lane = tid & 31, warp = tid >> 5;
  const int bm   = blockIdx.y, bn = blockIdx.x;
  const int NK   = K >> 6;                      // BK = 64

  if (tid == 0){
#pragma unroll
    for (int s = 0; s < 3; s++){
      MBAR_INIT(mbb + s*16,     128);           // full: 128 producer threads
      MBAR_INIT(mbb + s*16 + 8, 128);           // empty: 128 consumer threads
    }
  }
  __syncthreads();

  if (warp < 4){
    // ===================== CONSUMER: pure LDSM + MMA ======================
    const int wm = warp >> 1, wn = warp & 1;    // 2x2 grid of 64x64 warp tiles
    uint32_t rowA[4], rowB[4], kOff[4];
#pragma unroll
    for (int mt = 0; mt < 4; mt++)
      rowA[mt] = (uint32_t)((wm*64 + mt*16 + (lane & 15)) * 128);
#pragma unroll
    for (int j = 0; j < 4; j++)
      rowB[j]  = (uint32_t)((wn*64 + j*16 + ((lane>>3)&1)*8 + (lane&7)) * 128);
#pragma unroll
    for (int ks = 0; ks < 4; ks++)
      kOff[ks] = (uint32_t)(((2*ks + (lane>>4)) ^ (lane & 7)) << 4);

    float c[4][8][4];
#pragma unroll
    for (int i=0;i<4;i++)
#pragma unroll
      for (int j=0;j<8;j++)
#pragma unroll
        for (int q=0;q<4;q++) c[i][j][q]=0.f;

    uint32_t af[2][16], bf[2][16];
    int s = 0; uint32_t ph = 0;

    for (int kt = 0; kt < NK; kt++){
      MBAR_WAIT(mbb + s*16, ph);
      const uint32_t aB = sbase + (uint32_t)(s*STAGE);
      const uint32_t bB = aB + 16384u;
      // prime ks=0 fragments
#pragma unroll
      for (int mt = 0; mt < 4; mt++)
        LDSM4(af[0][mt*4+0],af[0][mt*4+1],af[0][mt*4+2],af[0][mt*4+3],
              aB + rowA[mt] + kOff[0]);
#pragma unroll
      for (int j = 0; j < 4; j++)
        LDSM4(bf[0][j*4+0],bf[0][j*4+1],bf[0][j*4+2],bf[0][j*4+3],
              bB + rowB[j] + kOff[0]);
#pragma unroll
      for (int ks = 0; ks < 4; ks++){
        const int cur = ks & 1, nxt = cur ^ 1;
        if (ks < 3){
#pragma unroll
          for (int mt = 0; mt < 4; mt++)
            LDSM4(af[nxt][mt*4+0],af[nxt][mt*4+1],af[nxt][mt*4+2],af[nxt][mt*4+3],
                  aB + rowA[mt] + kOff[ks+1]);
#pragma unroll
          for (int j = 0; j < 4; j++)
            LDSM4(bf[nxt][j*4+0],bf[nxt][j*4+1],bf[nxt][j*4+2],bf[nxt][j*4+3],
                  bB + rowB[j] + kOff[ks+1]);
        }
#pragma unroll
        for (int mt = 0; mt < 4; mt++)
#pragma unroll
          for (int nt = 0; nt < 8; nt++)
            MMA16(c[mt][nt],
                  af[cur][mt*4+0],af[cur][mt*4+1],af[cur][mt*4+2],af[cur][mt*4+3],
                  bf[cur][(nt>>1)*4 + (nt&1)], bf[cur][(nt>>1)*4 + (nt&1) + 2]);
      }
      MBAR_ARRIVE(mbb + s*16 + 8);
      if (++s == 3){ s = 0; ph ^= 1u; }
    }

    // epilogue
    const int g  = lane >> 2, t4 = lane & 3;
    const size_t rbase = (size_t)(bm*128 + wm*64);
    const int    cbase = bn*128 + wn*64 + 2*t4;
#pragma unroll
    for (int mt = 0; mt < 4; mt++){
#pragma unroll
      for (int nt = 0; nt < 8; nt++){
        size_t o0 = (rbase + mt*16 + g) * (size_t)N + cbase + nt*8;
        *reinterpret_cast<float2*>(C + o0) =
            make_float2(c[mt][nt][0], c[mt][nt][1]);
        *reinterpret_cast<float2*>(C + o0 + (size_t)8*N) =
            make_float2(c[mt][nt][2], c[mt][nt][3]);
      }
    }
  } else {
    // ===================== PRODUCER: cp.async A + dequant B ===============
    const int ptid = tid - 128;                 // 0..127
    const __half* Ag = g_A16 + (size_t)(bm*128 + ptid)*K;
    const int ngl = bn*128 + ptid;
    const int zsh = (ngl & 7) * 4;
    const int N8  = N >> 3;
    const uint32_t aoff = (uint32_t)(ptid*128);
    const uint32_t hx   = (uint32_t)(ptid & 7);

    unsigned wR[8];
    uint32_t zc2 = 0;
    __half2  s2  = __half2half2(__float2half(0.f));

    int s = 0; uint32_t ph = 1;                 // producer phase starts 1
    for (int kt = 0; kt < NK; kt++){
      // prefetch B words + group constants (overlaps the empty-wait)
      const int wrow = kt*8;
#pragma unroll
      for (int wi = 0; wi < 8; wi++)
        wR[wi] = (unsigned)QW[(size_t)(wrow+wi)*N + ngl];
      if ((kt & 1) == 0){                       // GROUP=128 = 2 k-tiles
        const int g  = kt >> 1;
        const int zq = (QZ[(size_t)g*N8 + (ngl>>3)] >> zsh) & 15;
        const uint32_t zb = 0x6400u + 1u + (uint32_t)zq;  // fp16 bits 1025+z
        zc2 = zb | (zb << 16);
        s2  = __half2half2(__float2half(SC[(size_t)g*N + ngl]));
      }

      MBAR_WAIT(mbb + s*16 + 8, ph);
      const uint32_t dA = sbase + (uint32_t)(s*STAGE);
      // A: one row per thread, 8 x 16B cp.async
      const __half* srcA = Ag + kt*64;
#pragma unroll
      for (int ch = 0; ch < 8; ch++)
        CPASYNC16(dA + aoff + (((uint32_t)ch ^ hx) << 4), srcA + ch*8);
      CPCOMMIT();
      // B: dequant 8 words -> 8 x STS.128
      char* sB = smem + s*STAGE + 16384;
#pragma unroll
      for (int wi = 0; wi < 8; wi++){
        unsigned w = wR[wi];
        uint32_t t[4];
#pragma unroll
        for (int jp = 0; jp < 4; jp++){
          uint32_t u = (w & 0xFu) | ((w << 12) & 0x000F0000u) | 0x64006400u;
          __half2 h = __hsub2(*reinterpret_cast<__half2*>(&u),
                              *reinterpret_cast<__half2*>(&zc2));
          h = __hmul2(h, s2);
          t[jp] = *reinterpret_cast<uint32_t*>(&h);
          w >>= 8;
        }
        *reinterpret_cast<uint4*>(sB + aoff + (((uint32_t)wi ^ hx) << 4)) =
            make_uint4(t[0], t[1], t[2], t[3]);
      }
      CPWAIT0();                                 // A landed
      MBAR_ARRIVE(mbb + s*16);                   // publish stage
      if (++s == 3){ s = 0; ph ^= 1u; }
    }
  }
}

extern "C" void kernel_launch(void* const* d_in, const int* in_sizes, int n_in,
                              void* d_out, int out_size)
{
  const float* x  = (const float*)d_in[0];
  const int*   qw = (const int*)  d_in[1];
  const float* sc = (const float*)d_in[2];
  const int*   qz = (const int*)  d_in[3];
  // d_in[4] = g_idx (standard consecutive grouping; used only for sizes)

  const int K = in_sizes[4];
  const int M = in_sizes[0] / K;
  const int G = K / 128;
  const int N = in_sizes[2] / G;

  const int total8 = (M * K) / 8;
  conv_a_kernel<<<(total8 + 255) / 256, 256>>>(x, total8);

  const int shmem = 3 * 32768 + 64;   // 3 stages + mbarriers
  cudaFuncSetAttribute(gptq_ws,
                       cudaFuncAttributeMaxDynamicSharedMemorySize, shmem);
  dim3 grid(N / 128, M / 128);
  gptq_ws<<<grid, 256, shmem>>>(qw, sc, qz, (float*)d_out, M, N, K);
}

// round 14
// speedup vs baseline: 1.0809x; 1.0809x over previous
#include <cuda_runtime.h>
#include <cuda_fp16.h>
#include <cstdint>

// ---------------------------------------------------------------------------
// GPTQ 4-bit dequant GEMM, fp16 mma.sync m16n8k16, fp32 accum.
// Pre-kernels: (0) repack QW to n-major + nibble-permuted, (1) A fp32->fp16.
// GEMM: tile 128x128x64, 8 warps (2x4, warp tile 64x32), 2-stage smem,
// __launch_bounds__(256,2) so 2 CTAs/SM overlap produce/compute phases.
// Smem rows 128B, XOR-8 16B-chunk swizzle.
// ---------------------------------------------------------------------------

__device__ __align__(16) __half g_A16[4096ull * 4096ull];     // 32 MB
__device__ __align__(16) unsigned g_QWr[11008ull * 512ull];   // 22.5 MB

#define LDSM4(R0,R1,R2,R3,addr) \
  asm volatile("ldmatrix.sync.aligned.m8n8.x4.shared.b16 {%0,%1,%2,%3}, [%4];" \
    : "=r"(R0),"=r"(R1),"=r"(R2),"=r"(R3) : "r"(addr))

#define MMA16(Cr,A0,A1,A2,A3,B0,B1) \
  asm volatile("mma.sync.aligned.m16n8k16.row.col.f32.f16.f16.f32 " \
    "{%0,%1,%2,%3},{%4,%5,%6,%7},{%8,%9},{%0,%1,%2,%3};" \
    : "+f"(Cr[0]),"+f"(Cr[1]),"+f"(Cr[2]),"+f"(Cr[3]) \
    : "r"(A0),"r"(A1),"r"(A2),"r"(A3),"r"(B0),"r"(B1))

#define CPASYNC16(dst, src) \
  asm volatile("cp.async.cg.shared.global [%0], [%1], 16;" :: "r"(dst), "l"(src))
#define CPCOMMIT() asm volatile("cp.async.commit_group;" ::: "memory")
#define CPWAIT0()  asm volatile("cp.async.wait_group 0;" ::: "memory")

__device__ __forceinline__ uint32_t f16x2(float lo, float hi){
  uint32_t r; asm("cvt.rn.f16x2.f32 %0, %2, %1;" : "=r"(r) : "f"(lo), "f"(hi)); return r;
}

// ---- kernel 0: repack QW.  new[n][kw] = nibble-permute(old[kw][n]).
// Permute: old even nibbles (k0,k2,k4,k6) -> positions 0..3,
//          old odd  nibbles (k1,k3,k5,k7) -> positions 4..7.
// Then (w>>4j) & 0x000F000F yields the half2 pair (k2j, k2j+1).
__global__ void __launch_bounds__(256)
repack_qw(const int* __restrict__ QW, int N, int KW){
  int idx = blockIdx.x * blockDim.x + threadIdx.x;
  if (idx >= N * KW) return;
  const int n = idx / KW, kw = idx - n * KW;
  const unsigned w = (unsigned)QW[(size_t)kw * N + n];
  unsigned nw =  (w         & 0xFu)
              | ((w >>  8) & 0xFu) <<  4
              | ((w >> 16) & 0xFu) <<  8
              | ((w >> 24) & 0xFu) << 12
              | ((w >>  4) & 0xFu) << 16
              | ((w >> 12) & 0xFu) << 20
              | ((w >> 20) & 0xFu) << 24
              | ((w >> 28) & 0xFu) << 28;
  g_QWr[idx] = nw;
}

// ---- kernel 1: A fp32 -> fp16 ----
__global__ void __launch_bounds__(256)
conv_a_kernel(const float* __restrict__ A, int total8){
  int i = blockIdx.x * blockDim.x + threadIdx.x;
  if (i >= total8) return;
  const float4* p = reinterpret_cast<const float4*>(A);
  float4 v0 = p[2*i], v1 = p[2*i+1];
  uint4 o;
  o.x = f16x2(v0.x, v0.y); o.y = f16x2(v0.z, v0.w);
  o.z = f16x2(v1.x, v1.y); o.w = f16x2(v1.z, v1.w);
  reinterpret_cast<uint4*>(g_A16)[i] = o;
}

// ---- kernel 2: GEMM ----
__global__ void __launch_bounds__(256, 2)
gptq_f16_2cta(const float* __restrict__ SC, const int* __restrict__ QZ,
              float* __restrict__ C, int M, int N, int K)
{
  // smem: 2 stages x (A 128x128B = 16KB, B 128x128B = 16KB)
  extern __shared__ char smem[];
  const int STAGE = 32768;
  const uint32_t sbase = (uint32_t)__cvta_generic_to_shared(smem);

  const int tid  = threadIdx.x;
  const int lane = tid & 31, warp = tid >> 5;
  const int wm   = warp >> 2, wn = warp & 3;     // 2 (M) x 4 (N); warp 64x32
  const int bm   = blockIdx.y, bn = blockIdx.x;
  const int NK   = K >> 6;                       // BK = 64
  const int KW   = K >> 3;                       // words per column (512)

  uint32_t rowA[4], rowB[2], kOff[4];
#pragma unroll
  for (int mt = 0; mt < 4; mt++)
    rowA[mt] = (uint32_t)((wm*64 + mt*16 + (lane & 15)) * 128);
#pragma unroll
  for (int j = 0; j < 2; j++)
    rowB[j]  = (uint32_t)((wn*32 + j*16 + ((lane>>3)&1)*8 + (lane&7)) * 128);
#pragma unroll
  for (int ks = 0; ks < 4; ks++)
    kOff[ks] = (uint32_t)(((2*ks + (lane>>4)) ^ (lane & 7)) << 4);

  // A cp.async: 2 threads/row, 4 x 16B chunks each
  const int ar  = tid >> 1;
  const int ac4 = (tid & 1) * 4;
  const __half* Ag = g_A16 + (size_t)(bm*128 + ar)*K;

  // B: thread owns n-row nn, k-half (4 words = 32 k)
  const int nn    = tid & 127;
  const int khalf = tid >> 7;
  const int ngl   = bn*128 + nn;
  const int zsh   = (ngl & 7) * 4;
  const int N8    = N >> 3;
  const unsigned* Bg = g_QWr + (size_t)ngl * KW + khalf*4;

  uint4    bw;
  uint32_t zc2 = 0;
  __half2  s2  = __half2half2(__float2half(0.f));

  float c[4][4][4];
#pragma unroll
  for (int i=0;i<4;i++)
#pragma unroll
    for (int j=0;j<4;j++)
#pragma unroll
      for (int q=0;q<4;q++) c[i][j][q]=0.f;

  auto CPA = [&](int kt, int stage){
    const uint32_t dbase = sbase + (uint32_t)(stage*STAGE);
    const __half* src = Ag + kt*64;
#pragma unroll
    for (int i = 0; i < 4; i++){
      const int ch = ac4 + i;
      const uint32_t off = (uint32_t)(ar*128) + (uint32_t)((ch ^ (ar&7)) << 4);
      CPASYNC16(dbase + off, src + ch*8);
    }
  };

  auto LDGB = [&](int kt){
    bw = *reinterpret_cast<const uint4*>(Bg + kt*8);
    if ((kt & 1) == 0){                          // GROUP=128 = 2 k-tiles
      const int g  = kt >> 1;
      const int zq = (QZ[(size_t)g*N8 + (ngl>>3)] >> zsh) & 15;
      const uint32_t zb = 0x6400u + 1u + (uint32_t)zq;   // fp16 bits of 1025+z
      zc2 = zb | (zb << 16);
      s2  = __half2half2(__float2half(SC[(size_t)g*N + ngl]));
    }
  };

  auto STOREB = [&](int stage){
    char* sB = smem + stage*STAGE + 16384;
    const unsigned wv[4] = { bw.x, bw.y, bw.z, bw.w };
#pragma unroll
    for (int wi = 0; wi < 4; wi++){
      const unsigned w = wv[wi];
      uint32_t t[4];
#pragma unroll
      for (int jp = 0; jp < 4; jp++){
        uint32_t u = ((w >> (4*jp)) & 0x000F000Fu) | 0x64006400u;
        __half2 h = __hsub2(*reinterpret_cast<__half2*>(&u),
                            *reinterpret_cast<__half2*>(&zc2));
        h = __hmul2(h, s2);
        t[jp] = *reinterpret_cast<uint32_t*>(&h);
      }
      const int ch = khalf*4 + wi;               // 16B chunk (8 k) index
      const uint32_t off = (uint32_t)(nn*128) + (uint32_t)((ch ^ (nn&7)) << 4);
      *reinterpret_cast<uint4*>(sB + off) = make_uint4(t[0], t[1], t[2], t[3]);
    }
  };

  auto COMPUTE = [&](int stage){
    const uint32_t aB = sbase + (uint32_t)(stage*STAGE);
    const uint32_t bB = aB + 16384u;
#pragma unroll
    for (int ks = 0; ks < 4; ks++){
      uint32_t af[4][4], bf[2][4];
#pragma unroll
      for (int mt = 0; mt < 4; mt++)
        LDSM4(af[mt][0],af[mt][1],af[mt][2],af[mt][3], aB + rowA[mt] + kOff[ks]);
#pragma unroll
      for (int j = 0; j < 2; j++)
        LDSM4(bf[j][0],bf[j][1],bf[j][2],bf[j][3], bB + rowB[j] + kOff[ks]);
#pragma unroll
      for (int mt = 0; mt < 4; mt++)
#pragma unroll
        for (int nt = 0; nt < 4; nt++)
          MMA16(c[mt][nt], af[mt][0],af[mt][1],af[mt][2],af[mt][3],
                bf[nt>>1][nt&1], bf[nt>>1][(nt&1)+2]);
    }
  };

  // ---- prologue ----
  CPA(0, 0); CPCOMMIT();
  LDGB(0);
  STOREB(0);
  CPWAIT0();
  __syncthreads();

  // ---- main loop ----
  for (int kt = 0; kt < NK; kt++){
    const int s = kt & 1;
    if (kt + 1 < NK){
      CPA(kt + 1, s ^ 1); CPCOMMIT();
      LDGB(kt + 1);
    }
    COMPUTE(s);
    if (kt + 1 < NK){
      STOREB(s ^ 1);
      CPWAIT0();
    }
    __syncthreads();
  }

  // ---- epilogue ----
  const int g  = lane >> 2, t4 = lane & 3;
  const size_t rbase = (size_t)(bm*128 + wm*64);
  const int    cbase = bn*128 + wn*32 + 2*t4;
#pragma unroll
  for (int mt = 0; mt < 4; mt++){
#pragma unroll
    for (int nt = 0; nt < 4; nt++){
      size_t o0 = (rbase + mt*16 + g) * (size_t)N + cbase + nt*8;
      *reinterpret_cast<float2*>(C + o0) =
          make_float2(c[mt][nt][0], c[mt][nt][1]);
      *reinterpret_cast<float2*>(C + o0 + (size_t)8*N) =
          make_float2(c[mt][nt][2], c[mt][nt][3]);
    }
  }
}

extern "C" void kernel_launch(void* const* d_in, const int* in_sizes, int n_in,
                              void* d_out, int out_size)
{
  const float* x  = (const float*)d_in[0];
  const int*   qw = (const int*)  d_in[1];
  const float* sc = (const float*)d_in[2];
  const int*   qz = (const int*)  d_in[3];
  // d_in[4] = g_idx (standard consecutive grouping; used only for sizes)

  const int K = in_sizes[4];
  const int M = in_sizes[0] / K;
  const int G = K / 128;
  const int N = in_sizes[2] / G;
  const int KW = K / 8;

  const int totw = N * KW;
  repack_qw<<<(totw + 255) / 256, 256>>>(qw, N, KW);

  const int total8 = (M * K) / 8;
  conv_a_kernel<<<(total8 + 255) / 256, 256>>>(x, total8);

  const int shmem = 2 * 32768;    // 64 KB
  cudaFuncSetAttribute(gptq_f16_2cta,
                       cudaFuncAttributeMaxDynamicSharedMemorySize, shmem);
  dim3 grid(N / 128, M / 128);
  gptq_f16_2cta<<<grid, 256, shmem>>>(sc, qz, (float*)d_out, M, N, K);
}

// round 16
// speedup vs baseline: 1.3025x; 1.2051x over previous
#include <cuda_runtime.h>
#include <cuda_fp16.h>
#include <cstdint>

// ---------------------------------------------------------------------------
// GPTQ 4-bit dequant GEMM, fp16 mma.sync m16n8k16, fp32 accum.
// Pre-kernels: (0) tiled-transpose repack QW (n-major + nibble permute),
//              (1) A fp32->fp16.
// GEMM: tile 128x128x64, 8 warps (2x4, warp tile 64x32), 2 CTAs/SM.
// 3-stage smem ring with per-stage mbarriers, NO __syncthreads in main loop:
// warps free-run with skew <= 2 kt; fast warps' produce phases are covered by
// slow warps' MMA streams.
// ---------------------------------------------------------------------------

__device__ __align__(16) __half g_A16[4096ull * 4096ull];     // 32 MB
__device__ __align__(16) unsigned g_QWr[11008ull * 512ull];   // 22.5 MB

#define LDSM4(R0,R1,R2,R3,addr) \
  asm volatile("ldmatrix.sync.aligned.m8n8.x4.shared.b16 {%0,%1,%2,%3}, [%4];" \
    : "=r"(R0),"=r"(R1),"=r"(R2),"=r"(R3) : "r"(addr))

#define MMA16(Cr,A0,A1,A2,A3,B0,B1) \
  asm volatile("mma.sync.aligned.m16n8k16.row.col.f32.f16.f16.f32 " \
    "{%0,%1,%2,%3},{%4,%5,%6,%7},{%8,%9},{%0,%1,%2,%3};" \
    : "+f"(Cr[0]),"+f"(Cr[1]),"+f"(Cr[2]),"+f"(Cr[3]) \
    : "r"(A0),"r"(A1),"r"(A2),"r"(A3),"r"(B0),"r"(B1))

#define CPASYNC16(dst, src) \
  asm volatile("cp.async.cg.shared.global [%0], [%1], 16;" :: "r"(dst), "l"(src))
#define CPCOMMIT() asm volatile("cp.async.commit_group;" ::: "memory")
#define CPWAIT0()  asm volatile("cp.async.wait_group 0;" ::: "memory")

#define MBAR_INIT(a, n) \
  asm volatile("mbarrier.init.shared.b64 [%0], %1;" :: "r"(a), "r"(n) : "memory")
#define MBAR_ARRIVE(a) \
  asm volatile("mbarrier.arrive.shared.b64 _, [%0];" :: "r"(a) : "memory")
#define MBAR_WAIT(a, ph) \
  asm volatile("{\n\t.reg .pred P;\n\tW%=:\n\t" \
    "mbarrier.try_wait.parity.acquire.cta.shared::cta.b64 P, [%0], %1;\n\t" \
    "@!P bra W%=;\n\t}" :: "r"(a), "r"(ph) : "memory")

__device__ __forceinline__ uint32_t f16x2(float lo, float hi){
  uint32_t r; asm("cvt.rn.f16x2.f32 %0, %2, %1;" : "=r"(r) : "f"(lo), "f"(hi)); return r;
}

// ---- kernel 0: repack QW via tiled transpose (coalesced both sides).
// new[n][kw] = nibble-permute(old[kw][n]); even nibbles -> low half,
// odd nibbles -> high half, so ((w>>4j) & 0x000F000F) is the (k2j,k2j+1) pair.
__global__ void __launch_bounds__(256)
repack_qw(const int* __restrict__ QW, int N, int KW){
  __shared__ unsigned t[32][33];
  const int tx = threadIdx.x, ty = threadIdx.y;       // (32, 8)
  const int n0 = blockIdx.x * 32, kw0 = blockIdx.y * 32;
#pragma unroll
  for (int i = 0; i < 4; i++)
    t[ty + 8*i][tx] = (unsigned)QW[(size_t)(kw0 + ty + 8*i) * N + (n0 + tx)];
  __syncthreads();
#pragma unroll
  for (int i = 0; i < 4; i++){
    const unsigned w = t[tx][ty + 8*i];
    unsigned nw =  (w         & 0xFu)
                | ((w >>  8) & 0xFu) <<  4
                | ((w >> 16) & 0xFu) <<  8
                | ((w >> 24) & 0xFu) << 12
                | ((w >>  4) & 0xFu) << 16
                | ((w >> 12) & 0xFu) << 20
                | ((w >> 20) & 0xFu) << 24
                | ((w >> 28) & 0xFu) << 28;
    g_QWr[(size_t)(n0 + ty + 8*i) * KW + (kw0 + tx)] = nw;
  }
}

// ---- kernel 1: A fp32 -> fp16 ----
__global__ void __launch_bounds__(256)
conv_a_kernel(const float* __restrict__ A, int total8){
  int i = blockIdx.x * blockDim.x + threadIdx.x;
  if (i >= total8) return;
  const float4* p = reinterpret_cast<const float4*>(A);
  float4 v0 = p[2*i], v1 = p[2*i+1];
  uint4 o;
  o.x = f16x2(v0.x, v0.y); o.y = f16x2(v0.z, v0.w);
  o.z = f16x2(v1.x, v1.y); o.w = f16x2(v1.z, v1.w);
  reinterpret_cast<uint4*>(g_A16)[i] = o;
}

// ---- kernel 2: GEMM, 3-stage mbarrier ring ----
__global__ void __launch_bounds__(256, 2)
gptq_ring(const float* __restrict__ SC, const int* __restrict__ QZ,
          float* __restrict__ C, int M, int N, int K)
{
  extern __shared__ char smem[];
  const int STAGE = 32768;                       // A 16KB + B 16KB
  const uint32_t sbase = (uint32_t)__cvta_generic_to_shared(smem);
  const uint32_t mbb   = sbase + 3*STAGE;        // full[s]=+16s, empty[s]=+16s+8

  const int tid  = threadIdx.x;
  const int lane = tid & 31, warp = tid >> 5;
  const int wm   = warp >> 2, wn = warp & 3;     // 2 (M) x 4 (N); warp 64x32
  const int bm   = blockIdx.y, bn = blockIdx.x;
  const int NK   = K >> 6;                       // BK = 64
  const int KW   = K >> 3;

  if (tid == 0){
#pragma unroll
    for (int s = 0; s < 3; s++){
      MBAR_INIT(mbb + s*16,     256);            // full
      MBAR_INIT(mbb + s*16 + 8, 256);            // empty
    }
  }
  __syncthreads();

  uint32_t rowA[4], rowB[2], kOff[4];
#pragma unroll
  for (int mt = 0; mt < 4; mt++)
    rowA[mt] = (uint32_t)((wm*64 + mt*16 + (lane & 15)) * 128);
#pragma unroll
  for (int j = 0; j < 2; j++)
    rowB[j]  = (uint32_t)((wn*32 + j*16 + ((lane>>3)&1)*8 + (lane&7)) * 128);
#pragma unroll
  for (int ks = 0; ks < 4; ks++)
    kOff[ks] = (uint32_t)(((2*ks + (lane>>4)) ^ (lane & 7)) << 4);

  // A cp.async: 2 threads/row, 4 x 16B chunks each
  const int ar  = tid >> 1;
  const int ac4 = (tid & 1) * 4;
  const __half* Ag = g_A16 + (size_t)(bm*128 + ar)*K;

  // B: thread owns n-row nn, k-half (4 words = 32 k)
  const int nn    = tid & 127;
  const int khalf = tid >> 7;
  const int ngl   = bn*128 + nn;
  const int zsh   = (ngl & 7) * 4;
  const int N8    = N >> 3;
  const unsigned* Bg = g_QWr + (size_t)ngl * KW + khalf*4;

  uint4    bw;
  uint32_t zc2 = 0;
  __half2  s2h = __half2half2(__float2half(0.f));

  float c[4][4][4];
#pragma unroll
  for (int i=0;i<4;i++)
#pragma unroll
    for (int j=0;j<4;j++)
#pragma unroll
      for (int q=0;q<4;q++) c[i][j][q]=0.f;

  auto LDGB = [&](int kt){
    bw = *reinterpret_cast<const uint4*>(Bg + kt*8);
    if ((kt & 1) == 0){                          // GROUP=128 = 2 k-tiles
      const int g  = kt >> 1;
      const int zq = (QZ[(size_t)g*N8 + (ngl>>3)] >> zsh) & 15;
      const uint32_t zb = 0x6400u + 1u + (uint32_t)zq;   // fp16 bits 1025+z
      zc2 = zb | (zb << 16);
      s2h = __half2half2(__float2half(SC[(size_t)g*N + ngl]));
    }
  };

  auto CPA = [&](int kt, int st){
    const uint32_t dbase = sbase + (uint32_t)(st*STAGE);
    const __half* src = Ag + kt*64;
#pragma unroll
    for (int i = 0; i < 4; i++){
      const int ch = ac4 + i;
      const uint32_t off = (uint32_t)(ar*128) + (uint32_t)((ch ^ (ar&7)) << 4);
      CPASYNC16(dbase + off, src + ch*8);
    }
  };

  auto STOREB = [&](int st){
    char* sB = smem + st*STAGE + 16384;
    const unsigned wv[4] = { bw.x, bw.y, bw.z, bw.w };
#pragma unroll
    for (int wi = 0; wi < 4; wi++){
      const unsigned w = wv[wi];
      uint32_t t[4];
#pragma unroll
      for (int jp = 0; jp < 4; jp++){
        uint32_t u = ((w >> (4*jp)) & 0x000F000Fu) | 0x64006400u;
        __half2 h = __hsub2(*reinterpret_cast<__half2*>(&u),
                            *reinterpret_cast<__half2*>(&zc2));
        h = __hmul2(h, s2h);
        t[jp] = *reinterpret_cast<uint32_t*>(&h);
      }
      const int ch = khalf*4 + wi;
      const uint32_t off = (uint32_t)(nn*128) + (uint32_t)((ch ^ (nn&7)) << 4);
      *reinterpret_cast<uint4*>(sB + off) = make_uint4(t[0], t[1], t[2], t[3]);
    }
  };

  auto COMPUTE = [&](int st){
    const uint32_t aB = sbase + (uint32_t)(st*STAGE);
    const uint32_t bB = aB + 16384u;
#pragma unroll
    for (int ks = 0; ks < 4; ks++){
      uint32_t af[4][4], bf[2][4];
#pragma unroll
      for (int mt = 0; mt < 4; mt++)
        LDSM4(af[mt][0],af[mt][1],af[mt][2],af[mt][3], aB + rowA[mt] + kOff[ks]);
#pragma unroll
      for (int j = 0; j < 2; j++)
        LDSM4(bf[j][0],bf[j][1],bf[j][2],bf[j][3], bB + rowB[j] + kOff[ks]);
#pragma unroll
      for (int mt = 0; mt < 4; mt++)
#pragma unroll
        for (int nt = 0; nt < 4; nt++)
          MMA16(c[mt][nt], af[mt][0],af[mt][1],af[mt][2],af[mt][3],
                bf[nt>>1][nt&1], bf[nt>>1][(nt&1)+2]);
    }
  };

  // ---- prologue: produce stages 0 and 1 (no empty-wait needed) ----
  LDGB(0); CPA(0, 0); CPCOMMIT(); STOREB(0); CPWAIT0(); MBAR_ARRIVE(mbb + 0*16);
  LDGB(1); CPA(1, 1); CPCOMMIT(); STOREB(1); CPWAIT0(); MBAR_ARRIVE(mbb + 1*16);

  // ---- main loop: consume s = kt%3, produce s2 = (kt+2)%3 ----
  int s = 0, sp = 2;
  uint32_t pf = 0u;        // full-parity bits per stage, init {0,0,0}
  uint32_t pe = 4u;        // empty-parity bits, init {0,0,1} (stage2 first)
  for (int kt = 0; kt < NK; kt++){
    const bool doP = (kt + 2 < NK);
    if (doP) LDGB(kt + 2);                      // LDG latency hides under MMAs

    MBAR_WAIT(mbb + s*16, (pf >> s) & 1u);
    pf ^= (1u << s);
    COMPUTE(s);
    MBAR_ARRIVE(mbb + s*16 + 8);

    if (doP){
      MBAR_WAIT(mbb + sp*16 + 8, (pe >> sp) & 1u);
      pe ^= (1u << sp);
      CPA(kt + 2, sp); CPCOMMIT();
      STOREB(sp);
      CPWAIT0();
      MBAR_ARRIVE(mbb + sp*16);
    }
    if (++s  == 3) s  = 0;
    if (++sp == 3) sp = 0;
  }

  // ---- epilogue ----
  const int g  = lane >> 2, t4 = lane & 3;
  const size_t rbase = (size_t)(bm*128 + wm*64);
  const int    cbase = bn*128 + wn*32 + 2*t4;
#pragma unroll
  for (int mt = 0; mt < 4; mt++){
#pragma unroll
    for (int nt = 0; nt < 4; nt++){
      size_t o0 = (rbase + mt*16 + g) * (size_t)N + cbase + nt*8;
      *reinterpret_cast<float2*>(C + o0) =
          make_float2(c[mt][nt][0], c[mt][nt][1]);
      *reinterpret_cast<float2*>(C + o0 + (size_t)8*N) =
          make_float2(c[mt][nt][2], c[mt][nt][3]);
    }
  }
}

extern "C" void kernel_launch(void* const* d_in, const int* in_sizes, int n_in,
                              void* d_out, int out_size)
{
  const float* x  = (const float*)d_in[0];
  const int*   qw = (const int*)  d_in[1];
  const float* sc = (const float*)d_in[2];
  const int*   qz = (const int*)  d_in[3];
  // d_in[4] = g_idx (standard consecutive grouping; used only for sizes)

  const int K = in_sizes[4];
  const int M = in_sizes[0] / K;
  const int G = K / 128;
  const int N = in_sizes[2] / G;
  const int KW = K / 8;

  dim3 tgrid(N / 32, KW / 32);
  repack_qw<<<tgrid, dim3(32, 8)>>>(qw, N, KW);

  const int total8 = (M * K) / 8;
  conv_a_kernel<<<(total8 + 255) / 256, 256>>>(x, total8);

  const int shmem = 3 * 32768 + 64;   // 3 stages + mbarriers
  cudaFuncSetAttribute(gptq_ring,
                       cudaFuncAttributeMaxDynamicSharedMemorySize, shmem);
  dim3 grid(N / 128, M / 128);
  gptq_ring<<<grid, 256, shmem>>>(sc, qz, (float*)d_out, M, N, K);
}